// round 1
// baseline (speedup 1.0000x reference)
#include <cuda_runtime.h>
#include <math.h>

#define T_TOK 2048
#define H_DIM 1024
#define F_DIM 4096
#define N_EXP 8

// ---------------- scratch (__device__ globals; no allocation allowed) -------
__device__ int   g_count[N_EXP];
__device__ int   g_offset[N_EXP];
__device__ int   g_tok_e[T_TOK * 2];
__device__ float g_tok_w[T_TOK * 2];
__device__ int   g_tok_rank[T_TOK * 2];
__device__ int   g_slot_token[T_TOK * 2];
__device__ int   g_slot_of[T_TOK * 2];
__device__ float g_act[(size_t)T_TOK * 2 * F_DIM];   // 64 MB: per-slot SwiGLU activations
__device__ float g_part[(size_t)T_TOK * 2 * H_DIM];  // 16 MB: per-slot down-proj partials

// ---------------- kernel 0: zero expert counters ----------------------------
__global__ void zero_counts_kernel() {
    if (threadIdx.x < N_EXP) g_count[threadIdx.x] = 0;
}

// ---------------- kernel 1: router (one warp per token) ---------------------
__global__ void router_kernel(const float* __restrict__ x,
                              const float* __restrict__ gw) {
    int gwarp = (blockIdx.x * blockDim.x + threadIdx.x) >> 5;
    int lane  = threadIdx.x & 31;
    if (gwarp >= T_TOK) return;
    const float* xr = x + (size_t)gwarp * H_DIM;

    float acc[N_EXP];
#pragma unroll
    for (int e = 0; e < N_EXP; e++) acc[e] = 0.f;

    for (int h = lane; h < H_DIM; h += 32) {
        float xv = xr[h];
        const float* g = gw + h * N_EXP;
#pragma unroll
        for (int e = 0; e < N_EXP; e++) acc[e] += xv * g[e];
    }
#pragma unroll
    for (int e = 0; e < N_EXP; e++) {
#pragma unroll
        for (int off = 16; off > 0; off >>= 1)
            acc[e] += __shfl_xor_sync(0xffffffffu, acc[e], off);
    }

    if (lane == 0) {
        // softmax over logits
        float m = acc[0];
#pragma unroll
        for (int e = 1; e < N_EXP; e++) m = fmaxf(m, acc[e]);
        float p[N_EXP], s = 0.f;
#pragma unroll
        for (int e = 0; e < N_EXP; e++) { p[e] = expf(acc[e] - m); s += p[e]; }
        float inv = 1.f / s;
#pragma unroll
        for (int e = 0; e < N_EXP; e++) p[e] *= inv;

        // top-2 of the probabilities (stable: first occurrence wins)
        int i0 = 0;
#pragma unroll
        for (int e = 1; e < N_EXP; e++) if (p[e] > p[i0]) i0 = e;
        int i1 = (i0 == 0) ? 1 : 0;
#pragma unroll
        for (int e = 0; e < N_EXP; e++)
            if (e != i0 && p[e] > p[i1]) i1 = e;

        // reference applies softmax to the top-k PROBABILITIES (not logits)
        float eb = expf(p[i1] - p[i0]);     // p[i1] <= p[i0]
        float w0 = 1.f / (1.f + eb);
        float w1 = eb * w0;

        int r0 = atomicAdd(&g_count[i0], 1);
        int r1 = atomicAdd(&g_count[i1], 1);
        g_tok_e[gwarp * 2 + 0]    = i0;
        g_tok_e[gwarp * 2 + 1]    = i1;
        g_tok_w[gwarp * 2 + 0]    = w0;
        g_tok_w[gwarp * 2 + 1]    = w1;
        g_tok_rank[gwarp * 2 + 0] = r0;
        g_tok_rank[gwarp * 2 + 1] = r1;
    }
}

// ---------------- kernel 2: prefix offsets + scatter slot map ---------------
__global__ void scan_scatter_kernel() {
    __shared__ int soff[N_EXP];
    if (threadIdx.x == 0) {
        int s = 0;
        for (int e = 0; e < N_EXP; e++) {
            soff[e] = s;
            g_offset[e] = s;
            s += g_count[e];
        }
    }
    __syncthreads();
    for (int t = threadIdx.x; t < T_TOK; t += blockDim.x) {
#pragma unroll
        for (int k = 0; k < 2; k++) {
            int e = g_tok_e[t * 2 + k];
            int slot = soff[e] + g_tok_rank[t * 2 + k];
            g_slot_token[slot] = t;
            g_slot_of[t * 2 + k] = slot;
        }
    }
}

// ---------------- kernel 3: fused gate+up GEMM + SwiGLU ---------------------
// per expert: [n_e,1024] x [1024,64-tile of 4096], dual output, 64x64x16 tiles
__global__ void __launch_bounds__(256)
gateup_kernel(const float* __restrict__ x,
              const float* __restrict__ wg_all,
              const float* __restrict__ wu_all) {
    int e = blockIdx.z;
    int n = g_count[e];
    int rowbase = blockIdx.y * 64;
    if (rowbase >= n) return;
    int off = g_offset[e];
    int f0  = blockIdx.x * 64;
    const float* wg = wg_all + (size_t)e * H_DIM * F_DIM;
    const float* wu = wu_all + (size_t)e * H_DIM * F_DIM;

    __shared__ __align__(16) float Xs[16][68];
    __shared__ __align__(16) float Gs[16][68];
    __shared__ __align__(16) float Us[16][68];

    int tid = threadIdx.x;
    int tx = tid & 15, ty = tid >> 4;

    int lrow = tid >> 2;         // 0..63  (A-tile row this thread loads)
    int lk4  = (tid & 3) << 2;   // 0,4,8,12
    bool rvalid = (rowbase + lrow) < n;
    int tok = 0;
    if (rvalid) tok = g_slot_token[off + rowbase + lrow];
    const float* xrow = x + (size_t)tok * H_DIM;

    int wk = tid >> 4;           // 0..15 (weight-tile row)
    int wc = (tid & 15) << 2;    // 0..60

    float accg[4][4], accu[4][4];
#pragma unroll
    for (int i = 0; i < 4; i++)
#pragma unroll
        for (int j = 0; j < 4; j++) { accg[i][j] = 0.f; accu[i][j] = 0.f; }

    for (int k0 = 0; k0 < H_DIM; k0 += 16) {
        float4 xv = make_float4(0.f, 0.f, 0.f, 0.f);
        if (rvalid) xv = *(const float4*)(xrow + k0 + lk4);
        Xs[lk4 + 0][lrow] = xv.x;
        Xs[lk4 + 1][lrow] = xv.y;
        Xs[lk4 + 2][lrow] = xv.z;
        Xs[lk4 + 3][lrow] = xv.w;
        *(float4*)&Gs[wk][wc] = *(const float4*)(wg + (size_t)(k0 + wk) * F_DIM + f0 + wc);
        *(float4*)&Us[wk][wc] = *(const float4*)(wu + (size_t)(k0 + wk) * F_DIM + f0 + wc);
        __syncthreads();
#pragma unroll
        for (int k = 0; k < 16; k++) {
            float4 a  = *(const float4*)&Xs[k][ty * 4];
            float4 bg = *(const float4*)&Gs[k][tx * 4];
            float4 bu = *(const float4*)&Us[k][tx * 4];
            float av[4]  = {a.x, a.y, a.z, a.w};
            float bgv[4] = {bg.x, bg.y, bg.z, bg.w};
            float buv[4] = {bu.x, bu.y, bu.z, bu.w};
#pragma unroll
            for (int i = 0; i < 4; i++)
#pragma unroll
                for (int j = 0; j < 4; j++) {
                    accg[i][j] = fmaf(av[i], bgv[j], accg[i][j]);
                    accu[i][j] = fmaf(av[i], buv[j], accu[i][j]);
                }
        }
        __syncthreads();
    }

#pragma unroll
    for (int i = 0; i < 4; i++) {
        int row = rowbase + ty * 4 + i;
        if (row < n) {
            float v[4];
#pragma unroll
            for (int j = 0; j < 4; j++) {
                float g = accg[i][j];
                float sil = g / (1.f + expf(-g));
                v[j] = sil * accu[i][j];
            }
            *(float4*)&g_act[(size_t)(off + row) * F_DIM + f0 + tx * 4] =
                make_float4(v[0], v[1], v[2], v[3]);
        }
    }
}

// ---------------- kernel 4: down projection GEMM ----------------------------
// per expert: [n_e,4096] x [4096,64-tile of 1024]
__global__ void __launch_bounds__(256)
down_kernel(const float* __restrict__ wd_all) {
    int e = blockIdx.z;
    int n = g_count[e];
    int rowbase = blockIdx.y * 64;
    if (rowbase >= n) return;
    int off = g_offset[e];
    int h0  = blockIdx.x * 64;
    const float* wd = wd_all + (size_t)e * F_DIM * H_DIM;

    __shared__ __align__(16) float As[16][68];
    __shared__ __align__(16) float Bs[16][68];

    int tid = threadIdx.x;
    int tx = tid & 15, ty = tid >> 4;

    int lrow = tid >> 2;
    int lk4  = (tid & 3) << 2;
    bool rvalid = (rowbase + lrow) < n;
    size_t arow = (size_t)(off + rowbase + lrow) * F_DIM;

    int wk = tid >> 4;
    int wc = (tid & 15) << 2;

    float acc[4][4];
#pragma unroll
    for (int i = 0; i < 4; i++)
#pragma unroll
        for (int j = 0; j < 4; j++) acc[i][j] = 0.f;

    for (int k0 = 0; k0 < F_DIM; k0 += 16) {
        float4 av = make_float4(0.f, 0.f, 0.f, 0.f);
        if (rvalid) av = *(const float4*)&g_act[arow + k0 + lk4];
        As[lk4 + 0][lrow] = av.x;
        As[lk4 + 1][lrow] = av.y;
        As[lk4 + 2][lrow] = av.z;
        As[lk4 + 3][lrow] = av.w;
        *(float4*)&Bs[wk][wc] = *(const float4*)(wd + (size_t)(k0 + wk) * H_DIM + h0 + wc);
        __syncthreads();
#pragma unroll
        for (int k = 0; k < 16; k++) {
            float4 a = *(const float4*)&As[k][ty * 4];
            float4 b = *(const float4*)&Bs[k][tx * 4];
            float avv[4] = {a.x, a.y, a.z, a.w};
            float bvv[4] = {b.x, b.y, b.z, b.w};
#pragma unroll
            for (int i = 0; i < 4; i++)
#pragma unroll
                for (int j = 0; j < 4; j++)
                    acc[i][j] = fmaf(avv[i], bvv[j], acc[i][j]);
        }
        __syncthreads();
    }

#pragma unroll
    for (int i = 0; i < 4; i++) {
        int row = rowbase + ty * 4 + i;
        if (row < n) {
            *(float4*)&g_part[(size_t)(off + row) * H_DIM + h0 + tx * 4] =
                make_float4(acc[i][0], acc[i][1], acc[i][2], acc[i][3]);
        }
    }
}

// ---------------- kernel 5: weighted combine (deterministic, no atomics) ----
__global__ void combine_kernel(float* __restrict__ out) {
    int idx = blockIdx.x * blockDim.x + threadIdx.x;
    if (idx >= T_TOK * H_DIM) return;
    int t = idx >> 10;       // H_DIM = 1024
    int h = idx & 1023;
    int   s0 = g_slot_of[t * 2 + 0];
    int   s1 = g_slot_of[t * 2 + 1];
    float w0 = g_tok_w[t * 2 + 0];
    float w1 = g_tok_w[t * 2 + 1];
    out[idx] = w0 * g_part[(size_t)s0 * H_DIM + h] +
               w1 * g_part[(size_t)s1 * H_DIM + h];
}

// ---------------- launch ----------------------------------------------------
extern "C" void kernel_launch(void* const* d_in, const int* in_sizes, int n_in,
                              void* d_out, int out_size) {
    const float* x      = (const float*)d_in[0];
    const float* gate_w = (const float*)d_in[1];
    const float* w_gate = (const float*)d_in[2];
    const float* w_up   = (const float*)d_in[3];
    const float* w_down = (const float*)d_in[4];
    float* out = (float*)d_out;

    zero_counts_kernel<<<1, 32>>>();
    router_kernel<<<T_TOK / 8, 256>>>(x, gate_w);     // 8 tokens (warps) per block
    scan_scatter_kernel<<<1, 256>>>();
    gateup_kernel<<<dim3(F_DIM / 64, T_TOK / 64, N_EXP), 256>>>(x, w_gate, w_up);
    down_kernel<<<dim3(H_DIM / 64, T_TOK / 64, N_EXP), 256>>>(w_down);
    combine_kernel<<<(T_TOK * H_DIM) / 256, 256>>>(out);
}

// round 2
// speedup vs baseline: 1.8238x; 1.8238x over previous
#include <cuda_runtime.h>
#include <cuda_bf16.h>
#include <math.h>
#include <stdint.h>

#define T_TOK 2048
#define H_DIM 1024
#define F_DIM 4096
#define N_EXP 8
#define NSLOT (T_TOK * 2)

#define ASTR 40   // A smem row stride in bf16 elems (32 + 8 pad) -> 80B, 16B aligned
#define BSTR 72   // B smem row stride in bf16 elems (64 + 8 pad) -> 144B, 16B aligned

// ---------------- scratch (__device__ globals) ------------------------------
__device__ int      g_count[N_EXP];
__device__ int      g_offset[N_EXP];
__device__ int      g_tok_e[NSLOT];
__device__ float    g_tok_w[NSLOT];
__device__ int      g_tok_rank[NSLOT];
__device__ int      g_slot_token[NSLOT];
__device__ int      g_slot_of[NSLOT];
__device__ uint16_t g_acth[(size_t)NSLOT * F_DIM];   // SwiGLU activations, bf16 hi
__device__ uint16_t g_actl[(size_t)NSLOT * F_DIM];   // SwiGLU activations, bf16 lo
__device__ float    g_part[(size_t)NSLOT * H_DIM];   // down-proj partials (fp32)

// ---------------- helpers ---------------------------------------------------
__device__ __forceinline__ uint32_t smem_u32(const void* p) {
    return (uint32_t)__cvta_generic_to_shared(p);
}
__device__ __forceinline__ void ldsm_x4(uint32_t* r, uint32_t addr) {
    asm volatile("ldmatrix.sync.aligned.m8n8.x4.shared.b16 {%0,%1,%2,%3},[%4];"
                 : "=r"(r[0]), "=r"(r[1]), "=r"(r[2]), "=r"(r[3]) : "r"(addr));
}
__device__ __forceinline__ void ldsm_x2t(uint32_t* r, uint32_t addr) {
    asm volatile("ldmatrix.sync.aligned.m8n8.x2.trans.shared.b16 {%0,%1},[%2];"
                 : "=r"(r[0]), "=r"(r[1]) : "r"(addr));
}
__device__ __forceinline__ void mma_bf16(float* c, const uint32_t* a, const uint32_t* b) {
    asm volatile(
        "mma.sync.aligned.m16n8k16.row.col.f32.bf16.bf16.f32 "
        "{%0,%1,%2,%3},{%4,%5,%6,%7},{%8,%9},{%0,%1,%2,%3};"
        : "+f"(c[0]), "+f"(c[1]), "+f"(c[2]), "+f"(c[3])
        : "r"(a[0]), "r"(a[1]), "r"(a[2]), "r"(a[3]), "r"(b[0]), "r"(b[1]));
}
// split two fp32 into packed bf16 (hi pair, lo pair); low 16 bits = first elem
__device__ __forceinline__ void split2(float v0, float v1, uint32_t& h, uint32_t& l) {
    __nv_bfloat16 h0 = __float2bfloat16_rn(v0);
    __nv_bfloat16 h1 = __float2bfloat16_rn(v1);
    __nv_bfloat16 l0 = __float2bfloat16_rn(v0 - __bfloat162float(h0));
    __nv_bfloat16 l1 = __float2bfloat16_rn(v1 - __bfloat162float(h1));
    h = (uint32_t)*(uint16_t*)&h0 | ((uint32_t)*(uint16_t*)&h1 << 16);
    l = (uint32_t)*(uint16_t*)&l0 | ((uint32_t)*(uint16_t*)&l1 << 16);
}

// ---------------- kernel 0: zero expert counters ----------------------------
__global__ void zero_counts_kernel() {
    if (threadIdx.x < N_EXP) g_count[threadIdx.x] = 0;
}

// ---------------- kernel 1: router (one warp per token) ---------------------
__global__ void router_kernel(const float* __restrict__ x,
                              const float* __restrict__ gw) {
    int gwarp = (blockIdx.x * blockDim.x + threadIdx.x) >> 5;
    int lane  = threadIdx.x & 31;
    if (gwarp >= T_TOK) return;
    const float* xr = x + (size_t)gwarp * H_DIM;

    float acc[N_EXP];
#pragma unroll
    for (int e = 0; e < N_EXP; e++) acc[e] = 0.f;
    for (int h = lane; h < H_DIM; h += 32) {
        float xv = xr[h];
        const float* g = gw + h * N_EXP;
#pragma unroll
        for (int e = 0; e < N_EXP; e++) acc[e] += xv * g[e];
    }
#pragma unroll
    for (int e = 0; e < N_EXP; e++) {
#pragma unroll
        for (int off = 16; off > 0; off >>= 1)
            acc[e] += __shfl_xor_sync(0xffffffffu, acc[e], off);
    }
    if (lane == 0) {
        float m = acc[0];
#pragma unroll
        for (int e = 1; e < N_EXP; e++) m = fmaxf(m, acc[e]);
        float p[N_EXP], s = 0.f;
#pragma unroll
        for (int e = 0; e < N_EXP; e++) { p[e] = expf(acc[e] - m); s += p[e]; }
        float inv = 1.f / s;
#pragma unroll
        for (int e = 0; e < N_EXP; e++) p[e] *= inv;

        int i0 = 0;
#pragma unroll
        for (int e = 1; e < N_EXP; e++) if (p[e] > p[i0]) i0 = e;
        int i1 = (i0 == 0) ? 1 : 0;
#pragma unroll
        for (int e = 0; e < N_EXP; e++)
            if (e != i0 && p[e] > p[i1]) i1 = e;

        float eb = expf(p[i1] - p[i0]);
        float w0 = 1.f / (1.f + eb);
        float w1 = eb * w0;

        int r0 = atomicAdd(&g_count[i0], 1);
        int r1 = atomicAdd(&g_count[i1], 1);
        g_tok_e[gwarp * 2 + 0]    = i0;
        g_tok_e[gwarp * 2 + 1]    = i1;
        g_tok_w[gwarp * 2 + 0]    = w0;
        g_tok_w[gwarp * 2 + 1]    = w1;
        g_tok_rank[gwarp * 2 + 0] = r0;
        g_tok_rank[gwarp * 2 + 1] = r1;
    }
}

// ---------------- kernel 2: prefix offsets + scatter slot map ---------------
__global__ void scan_scatter_kernel() {
    __shared__ int soff[N_EXP];
    if (threadIdx.x == 0) {
        int s = 0;
        for (int e = 0; e < N_EXP; e++) { soff[e] = s; g_offset[e] = s; s += g_count[e]; }
    }
    __syncthreads();
    for (int t = threadIdx.x; t < T_TOK; t += blockDim.x) {
#pragma unroll
        for (int k = 0; k < 2; k++) {
            int e = g_tok_e[t * 2 + k];
            int slot = soff[e] + g_tok_rank[t * 2 + k];
            g_slot_token[slot] = t;
            g_slot_of[t * 2 + k] = slot;
        }
    }
}

// ---------------- kernel 3: fused gate+up tensor-core GEMM + SwiGLU ---------
// block tile 128(M) x 64(N), K-tile 32; 8 warps (4x2), warp tile 32x32.
// 3-term bf16 split for fp32-grade precision.
__global__ void __launch_bounds__(256)
gateup_kernel(const float* __restrict__ x,
              const float* __restrict__ wg_all,
              const float* __restrict__ wu_all) {
    int e = blockIdx.z;
    int n = g_count[e];
    int rowbase = blockIdx.y * 128;
    if (rowbase >= n) return;
    int off = g_offset[e];
    int f0  = blockIdx.x * 64;
    const float* wg = wg_all + (size_t)e * H_DIM * F_DIM;
    const float* wu = wu_all + (size_t)e * H_DIM * F_DIM;

    __shared__ __align__(16) uint16_t Ah[128 * ASTR], Al[128 * ASTR];
    __shared__ __align__(16) uint16_t Bgh[32 * BSTR], Bgl[32 * BSTR];
    __shared__ __align__(16) uint16_t Buh[32 * BSTR], Bul[32 * BSTR];

    int tid = threadIdx.x, lane = tid & 31, wid = tid >> 5;
    int warp_m = wid >> 1, warp_n = wid & 1;

    // A loader: 2 threads per row, 16 k-floats each
    int arow = tid >> 1, ahalf = tid & 1;
    bool rvalid = (rowbase + arow) < n;
    const float* xrow = x;
    if (rvalid)
        xrow = x + (size_t)g_slot_token[off + rowbase + arow] * H_DIM + ahalf * 16;
    // B loader: 8 threads per k-row, 8 n-floats each
    int bk = tid >> 3, bn = (tid & 7) * 8;
    const float* wgp = wg + (size_t)bk * F_DIM + f0 + bn;
    const float* wup = wu + (size_t)bk * F_DIM + f0 + bn;

    float accg[2][4][4], accu[2][4][4];
#pragma unroll
    for (int i = 0; i < 2; i++)
#pragma unroll
        for (int j = 0; j < 4; j++)
#pragma unroll
            for (int q = 0; q < 4; q++) { accg[i][j][q] = 0.f; accu[i][j][q] = 0.f; }

    float fa[16], fg[8], fu[8];

    // prologue: global load k-tile 0
#pragma unroll
    for (int j = 0; j < 4; j++) {
        float4 v = rvalid ? *(const float4*)(xrow + 4 * j) : make_float4(0, 0, 0, 0);
        fa[4 * j] = v.x; fa[4 * j + 1] = v.y; fa[4 * j + 2] = v.z; fa[4 * j + 3] = v.w;
    }
    {
        float4 v0 = *(const float4*)(wgp), v1 = *(const float4*)(wgp + 4);
        fg[0]=v0.x; fg[1]=v0.y; fg[2]=v0.z; fg[3]=v0.w; fg[4]=v1.x; fg[5]=v1.y; fg[6]=v1.z; fg[7]=v1.w;
        float4 u0 = *(const float4*)(wup), u1 = *(const float4*)(wup + 4);
        fu[0]=u0.x; fu[1]=u0.y; fu[2]=u0.z; fu[3]=u0.w; fu[4]=u1.x; fu[5]=u1.y; fu[6]=u1.z; fu[7]=u1.w;
    }

    const int KT = H_DIM / 32;
    for (int kt = 0; kt < KT; kt++) {
        // split + store to smem
        {
            uint32_t ph[8], pl[8];
#pragma unroll
            for (int j = 0; j < 8; j++) split2(fa[2 * j], fa[2 * j + 1], ph[j], pl[j]);
            *(uint4*)(Ah + arow * ASTR + ahalf * 16)     = *(uint4*)&ph[0];
            *(uint4*)(Ah + arow * ASTR + ahalf * 16 + 8) = *(uint4*)&ph[4];
            *(uint4*)(Al + arow * ASTR + ahalf * 16)     = *(uint4*)&pl[0];
            *(uint4*)(Al + arow * ASTR + ahalf * 16 + 8) = *(uint4*)&pl[4];
            uint32_t gh[4], gl[4], uh[4], ul[4];
#pragma unroll
            for (int j = 0; j < 4; j++) {
                split2(fg[2 * j], fg[2 * j + 1], gh[j], gl[j]);
                split2(fu[2 * j], fu[2 * j + 1], uh[j], ul[j]);
            }
            *(uint4*)(Bgh + bk * BSTR + bn) = *(uint4*)&gh[0];
            *(uint4*)(Bgl + bk * BSTR + bn) = *(uint4*)&gl[0];
            *(uint4*)(Buh + bk * BSTR + bn) = *(uint4*)&uh[0];
            *(uint4*)(Bul + bk * BSTR + bn) = *(uint4*)&ul[0];
        }
        __syncthreads();

        // prefetch next k-tile to registers
        if (kt + 1 < KT) {
            int k0 = (kt + 1) * 32;
#pragma unroll
            for (int j = 0; j < 4; j++) {
                float4 v = rvalid ? *(const float4*)(xrow + k0 + 4 * j) : make_float4(0, 0, 0, 0);
                fa[4 * j] = v.x; fa[4 * j + 1] = v.y; fa[4 * j + 2] = v.z; fa[4 * j + 3] = v.w;
            }
            const float* pg = wgp + (size_t)k0 * F_DIM;
            const float* pu = wup + (size_t)k0 * F_DIM;
            float4 v0 = *(const float4*)(pg), v1 = *(const float4*)(pg + 4);
            fg[0]=v0.x; fg[1]=v0.y; fg[2]=v0.z; fg[3]=v0.w; fg[4]=v1.x; fg[5]=v1.y; fg[6]=v1.z; fg[7]=v1.w;
            float4 u0 = *(const float4*)(pu), u1 = *(const float4*)(pu + 4);
            fu[0]=u0.x; fu[1]=u0.y; fu[2]=u0.z; fu[3]=u0.w; fu[4]=u1.x; fu[5]=u1.y; fu[6]=u1.z; fu[7]=u1.w;
        }

        // compute: 2 k-steps of 16
#pragma unroll
        for (int s = 0; s < 2; s++) {
            uint32_t ah[2][4], al[2][4];
            int r8 = lane & 7, tsel = lane >> 3;
            int acol = s * 16 + (tsel >> 1) * 8;
#pragma unroll
            for (int mt = 0; mt < 2; mt++) {
                int ar = warp_m * 32 + mt * 16 + r8 + (tsel & 1) * 8;
                ldsm_x4(ah[mt], smem_u32(Ah + ar * ASTR + acol));
                ldsm_x4(al[mt], smem_u32(Al + ar * ASTR + acol));
            }
            int bkr = s * 16 + (lane & 7) + ((lane >> 3) & 1) * 8;
#pragma unroll
            for (int nt = 0; nt < 4; nt++) {
                int nn = warp_n * 32 + nt * 8;
                uint32_t bh[2], bl[2], uh2[2], ul2[2];
                ldsm_x2t(bh,  smem_u32(Bgh + bkr * BSTR + nn));
                ldsm_x2t(bl,  smem_u32(Bgl + bkr * BSTR + nn));
                ldsm_x2t(uh2, smem_u32(Buh + bkr * BSTR + nn));
                ldsm_x2t(ul2, smem_u32(Bul + bkr * BSTR + nn));
#pragma unroll
                for (int mt = 0; mt < 2; mt++) {
                    mma_bf16(accg[mt][nt], ah[mt], bh);
                    mma_bf16(accg[mt][nt], ah[mt], bl);
                    mma_bf16(accg[mt][nt], al[mt], bh);
                    mma_bf16(accu[mt][nt], ah[mt], uh2);
                    mma_bf16(accu[mt][nt], ah[mt], ul2);
                    mma_bf16(accu[mt][nt], al[mt], uh2);
                }
            }
        }
        __syncthreads();
    }

    // epilogue: SwiGLU + split-store activations
    int gq = lane >> 2, tq = lane & 3;
#pragma unroll
    for (int mt = 0; mt < 2; mt++)
#pragma unroll
        for (int nt = 0; nt < 4; nt++) {
            int fc = f0 + warp_n * 32 + nt * 8 + tq * 2;
#pragma unroll
            for (int h2 = 0; h2 < 2; h2++) {
                int row = rowbase + warp_m * 32 + mt * 16 + gq + h2 * 8;
                if (row < n) {
                    float g0 = accg[mt][nt][h2 * 2],     g1 = accg[mt][nt][h2 * 2 + 1];
                    float u0 = accu[mt][nt][h2 * 2],     u1 = accu[mt][nt][h2 * 2 + 1];
                    float v0 = g0 / (1.f + expf(-g0)) * u0;
                    float v1 = g1 / (1.f + expf(-g1)) * u1;
                    uint32_t hh, ll;
                    split2(v0, v1, hh, ll);
                    size_t base = (size_t)(off + row) * F_DIM + fc;
                    *(uint32_t*)(g_acth + base) = hh;
                    *(uint32_t*)(g_actl + base) = ll;
                }
            }
        }
}

// ---------------- kernel 4: down projection tensor-core GEMM ----------------
__global__ void __launch_bounds__(256)
down_kernel(const float* __restrict__ wd_all) {
    int e = blockIdx.z;
    int n = g_count[e];
    int rowbase = blockIdx.y * 128;
    if (rowbase >= n) return;
    int off = g_offset[e];
    int h0  = blockIdx.x * 64;
    const float* wd = wd_all + (size_t)e * F_DIM * H_DIM;

    __shared__ __align__(16) uint16_t Ah[128 * ASTR], Al[128 * ASTR];
    __shared__ __align__(16) uint16_t Bh[32 * BSTR], Bl[32 * BSTR];

    int tid = threadIdx.x, lane = tid & 31, wid = tid >> 5;
    int warp_m = wid >> 1, warp_n = wid & 1;

    int arow = tid >> 1, ahalf = tid & 1;
    bool rvalid = (rowbase + arow) < n;
    const uint16_t* aph = g_acth + (size_t)(off + rowbase + arow) * F_DIM + ahalf * 16;
    const uint16_t* apl = g_actl + (size_t)(off + rowbase + arow) * F_DIM + ahalf * 16;
    int bk = tid >> 3, bn = (tid & 7) * 8;
    const float* wdp = wd + (size_t)bk * H_DIM + h0 + bn;

    float acc[2][4][4];
#pragma unroll
    for (int i = 0; i < 2; i++)
#pragma unroll
        for (int j = 0; j < 4; j++)
#pragma unroll
            for (int q = 0; q < 4; q++) acc[i][j][q] = 0.f;

    uint4 vh0, vh1, vl0, vl1;
    float fb[8];
    const uint4 z4 = make_uint4(0, 0, 0, 0);

    // prologue
    vh0 = rvalid ? *(const uint4*)(aph)     : z4;
    vh1 = rvalid ? *(const uint4*)(aph + 8) : z4;
    vl0 = rvalid ? *(const uint4*)(apl)     : z4;
    vl1 = rvalid ? *(const uint4*)(apl + 8) : z4;
    {
        float4 v0 = *(const float4*)(wdp), v1 = *(const float4*)(wdp + 4);
        fb[0]=v0.x; fb[1]=v0.y; fb[2]=v0.z; fb[3]=v0.w; fb[4]=v1.x; fb[5]=v1.y; fb[6]=v1.z; fb[7]=v1.w;
    }

    const int KT = F_DIM / 32;
    for (int kt = 0; kt < KT; kt++) {
        *(uint4*)(Ah + arow * ASTR + ahalf * 16)     = vh0;
        *(uint4*)(Ah + arow * ASTR + ahalf * 16 + 8) = vh1;
        *(uint4*)(Al + arow * ASTR + ahalf * 16)     = vl0;
        *(uint4*)(Al + arow * ASTR + ahalf * 16 + 8) = vl1;
        {
            uint32_t bh[4], bl[4];
#pragma unroll
            for (int j = 0; j < 4; j++) split2(fb[2 * j], fb[2 * j + 1], bh[j], bl[j]);
            *(uint4*)(Bh + bk * BSTR + bn) = *(uint4*)&bh[0];
            *(uint4*)(Bl + bk * BSTR + bn) = *(uint4*)&bl[0];
        }
        __syncthreads();

        if (kt + 1 < KT) {
            int k0 = (kt + 1) * 32;
            vh0 = rvalid ? *(const uint4*)(aph + k0)     : z4;
            vh1 = rvalid ? *(const uint4*)(aph + k0 + 8) : z4;
            vl0 = rvalid ? *(const uint4*)(apl + k0)     : z4;
            vl1 = rvalid ? *(const uint4*)(apl + k0 + 8) : z4;
            const float* p = wdp + (size_t)k0 * H_DIM;
            float4 v0 = *(const float4*)(p), v1 = *(const float4*)(p + 4);
            fb[0]=v0.x; fb[1]=v0.y; fb[2]=v0.z; fb[3]=v0.w; fb[4]=v1.x; fb[5]=v1.y; fb[6]=v1.z; fb[7]=v1.w;
        }

#pragma unroll
        for (int s = 0; s < 2; s++) {
            uint32_t ah[2][4], al[2][4];
            int r8 = lane & 7, tsel = lane >> 3;
            int acol = s * 16 + (tsel >> 1) * 8;
#pragma unroll
            for (int mt = 0; mt < 2; mt++) {
                int ar = warp_m * 32 + mt * 16 + r8 + (tsel & 1) * 8;
                ldsm_x4(ah[mt], smem_u32(Ah + ar * ASTR + acol));
                ldsm_x4(al[mt], smem_u32(Al + ar * ASTR + acol));
            }
            int bkr = s * 16 + (lane & 7) + ((lane >> 3) & 1) * 8;
#pragma unroll
            for (int nt = 0; nt < 4; nt++) {
                int nn = warp_n * 32 + nt * 8;
                uint32_t bh[2], bl[2];
                ldsm_x2t(bh, smem_u32(Bh + bkr * BSTR + nn));
                ldsm_x2t(bl, smem_u32(Bl + bkr * BSTR + nn));
#pragma unroll
                for (int mt = 0; mt < 2; mt++) {
                    mma_bf16(acc[mt][nt], ah[mt], bh);
                    mma_bf16(acc[mt][nt], ah[mt], bl);
                    mma_bf16(acc[mt][nt], al[mt], bh);
                }
            }
        }
        __syncthreads();
    }

    int gq = lane >> 2, tq = lane & 3;
#pragma unroll
    for (int mt = 0; mt < 2; mt++)
#pragma unroll
        for (int nt = 0; nt < 4; nt++) {
            int hc = h0 + warp_n * 32 + nt * 8 + tq * 2;
#pragma unroll
            for (int h2 = 0; h2 < 2; h2++) {
                int row = rowbase + warp_m * 32 + mt * 16 + gq + h2 * 8;
                if (row < n) {
                    float2 v = make_float2(acc[mt][nt][h2 * 2], acc[mt][nt][h2 * 2 + 1]);
                    *(float2*)(g_part + (size_t)(off + row) * H_DIM + hc) = v;
                }
            }
        }
}

// ---------------- kernel 5: weighted combine --------------------------------
__global__ void combine_kernel(float* __restrict__ out) {
    int idx = blockIdx.x * blockDim.x + threadIdx.x;
    if (idx >= T_TOK * H_DIM) return;
    int t = idx >> 10;
    int h = idx & 1023;
    int   s0 = g_slot_of[t * 2 + 0];
    int   s1 = g_slot_of[t * 2 + 1];
    float w0 = g_tok_w[t * 2 + 0];
    float w1 = g_tok_w[t * 2 + 1];
    out[idx] = w0 * g_part[(size_t)s0 * H_DIM + h] +
               w1 * g_part[(size_t)s1 * H_DIM + h];
}

// ---------------- launch ----------------------------------------------------
extern "C" void kernel_launch(void* const* d_in, const int* in_sizes, int n_in,
                              void* d_out, int out_size) {
    const float* x      = (const float*)d_in[0];
    const float* gate_w = (const float*)d_in[1];
    const float* w_gate = (const float*)d_in[2];
    const float* w_up   = (const float*)d_in[3];
    const float* w_down = (const float*)d_in[4];
    float* out = (float*)d_out;

    zero_counts_kernel<<<1, 32>>>();
    router_kernel<<<T_TOK / 8, 256>>>(x, gate_w);
    scan_scatter_kernel<<<1, 256>>>();
    gateup_kernel<<<dim3(F_DIM / 64, NSLOT / 128, N_EXP), 256>>>(x, w_gate, w_up);
    down_kernel<<<dim3(H_DIM / 64, NSLOT / 128, N_EXP), 256>>>(w_down);
    combine_kernel<<<(T_TOK * H_DIM) / 256, 256>>>(out);
}